// round 15
// baseline (speedup 1.0000x reference)
#include <cuda_runtime.h>
#include <cuda_fp16.h>
#include <cstdint>

// ---------------- problem constants ----------------
#define M_DIM 8192
#define K_DIM 4096
#define N_DIM 11008
#define NZ_DIM 1376
#define GS 128

// ---------------- GEMM tile config (R10/R12 winner shape) ----------------
#define BM 128
#define BN 256
#define BK 64                 // 64 halves -> 128B rows
#define NSTAGES (K_DIM / BK)  // 64
#define SPIPE 4
#define GRPM 8

#define A_STAGE_BYTES (BM * 128)   // 16384
#define B_STAGE_BYTES (BN * 128)   // 32768
#define STAGE_BYTES (A_STAGE_BYTES + B_STAGE_BYTES)
#define SMEM_TOTAL (SPIPE * STAGE_BYTES)   // 196608

#define MTILES (M_DIM / BM)   // 64
#define NTILES (N_DIM / BN)   // 43

// prep grid split
#define PREP_A_BLOCKS (M_DIM * (K_DIM / 8) / 256)   // 16384  (one 8-k chunk / thread)
#define PREP_W_BLOCKS ((N_DIM / 256) * (K_DIM / 8)) // 22016

// K-permutation within each row (period 16 k):
//   8B unit u = 4*kb + tg  holds halves {16kb+2tg, 16kb+2tg+1, 16kb+8+2tg, 16kb+8+2tg+1}
// => fragment pairs (k-lo word, k-hi word) are 8B-adjacent -> LDS.64.

// ---------------- scratch (k-permuted fp16) ----------------
__device__ __half g_wt[(size_t)N_DIM * K_DIM];   // dequant W^T: [N, K] permuted
__device__ __half g_ax[(size_t)M_DIM * K_DIM];   // x: [M, K] permuted

// ---------------- helpers ----------------
__device__ __forceinline__ uint32_t h2_as_u32(__half2 h) {
    union { __half2 h; uint32_t u; } cvt;
    cvt.h = h;
    return cvt.u;
}
__device__ __forceinline__ void cp16(uint32_t saddr, const void* g) {
    asm volatile("cp.async.cg.shared.global [%0], [%1], 16;" :: "r"(saddr), "l"(g));
}
__device__ __forceinline__ void cp_commit() { asm volatile("cp.async.commit_group;" ::: "memory"); }
__device__ __forceinline__ void cp_wait3()  { asm volatile("cp.async.wait_group 3;" ::: "memory"); }
__device__ __forceinline__ uint32_t smem_u32(const void* p) {
    uint32_t a;
    asm("{ .reg .u64 t; cvta.to.shared.u64 t, %1; cvt.u32.u64 %0, t; }" : "=r"(a) : "l"(p));
    return a;
}

// write 8 consecutive-k halves (as 4 packed uint32 pairs) to a permuted row
// kp = k0/8 within the row; rowbase = row base (half*)
__device__ __forceinline__ void store_perm8(__half* rowbase, int kp, const uint32_t* pairs) {
    int kb = kp >> 1;           // 16-k block
    int r8 = kp & 1;            // lo/hi half of the block
    char* base = (char*)rowbase + kb * 32 + r8 * 4;
    #pragma unroll
    for (int tg = 0; tg < 4; tg++)
        *(uint32_t*)(base + tg * 8) = pairs[tg];
}

// ---------------- merged prep: x->fp16 perm AND dequant W->fp16 perm [N,K] ----------------
extern "C" __global__ void prep_kernel(const float4* __restrict__ x,
                                       const uint32_t* __restrict__ qweight,
                                       const float* __restrict__ scales,
                                       const uint32_t* __restrict__ qzeros) {
    int b = blockIdx.x;
    if (b < PREP_A_BLOCKS) {
        size_t i = (size_t)b * 256 + threadIdx.x;       // 0 .. M*(K/8)-1
        int m  = (int)(i >> 9);                          // 512 chunks/row
        int kp = (int)(i & 511);
        const float4* src = x + ((size_t)m * K_DIM + kp * 8) / 4;
        float4 v0 = src[0];
        float4 v1 = src[1];
        uint32_t p[4];
        p[0] = h2_as_u32(__float22half2_rn(make_float2(v0.x, v0.y)));
        p[1] = h2_as_u32(__float22half2_rn(make_float2(v0.z, v0.w)));
        p[2] = h2_as_u32(__float22half2_rn(make_float2(v1.x, v1.y)));
        p[3] = h2_as_u32(__float22half2_rn(make_float2(v1.z, v1.w)));
        store_perm8(g_ax + (size_t)m * K_DIM, kp, p);
    } else {
        int b2 = b - PREP_A_BLOCKS;
        int n  = (b2 % (N_DIM / 256)) * 256 + threadIdx.x;   // 0..11007
        int kp = b2 / (N_DIM / 256);                         // 0..511
        int g  = kp >> 4;
        uint32_t q  = qweight[(size_t)kp * N_DIM + n];
        float    s  = scales[(size_t)g * N_DIM + n];
        uint32_t zq = qzeros[(size_t)g * NZ_DIM + (n >> 3)];
        float    sz = s * (float)((zq >> ((n & 7) * 4)) & 0xF);
        uint32_t p[4];
        #pragma unroll
        for (int j = 0; j < 4; j++) {
            float w0 = fmaf(s, (float)((q >> (8 * j))     & 0xF), -sz);
            float w1 = fmaf(s, (float)((q >> (8 * j + 4)) & 0xF), -sz);
            p[j] = h2_as_u32(__float22half2_rn(make_float2(w0, w1)));
        }
        store_perm8(g_wt + (size_t)n * K_DIM, kp, p);
    }
}

// ---------------- main GEMM: fp16 m16n8k16, LDS.64 fragment feed ----------------
extern "C" __global__ void __launch_bounds__(256, 1)
qgemm_f16(float* __restrict__ out) {
    extern __shared__ char smem[];
    uint32_t sb = smem_u32(smem);

    const int t = threadIdx.x;
    const int warp = t >> 5, lane = t & 31;
    const int g8 = lane >> 2, tg = lane & 3;
    const int warp_m = warp >> 2;    // 0..1 -> 64 rows
    const int warp_n = warp & 3;     // 0..3 -> 64 cols

    const int bid   = blockIdx.x;
    const int group = bid / (GRPM * NTILES);
    const int rem   = bid % (GRPM * NTILES);
    const int m0    = (group * GRPM + (rem % GRPM)) * BM;
    const int n0    = (rem / GRPM) * BN;

    float c[4][8][4];
    #pragma unroll
    for (int i = 0; i < 4; i++)
        #pragma unroll
        for (int j = 0; j < 8; j++)
            #pragma unroll
            for (int k = 0; k < 4; k++) c[i][j][k] = 0.f;

    // ---- cp.async addresses; 16B granule G stored at G ^ ((row&3)<<1) ----
    const __half* a_g[4]; uint32_t a_s[4];
    #pragma unroll
    for (int i = 0; i < 4; i++) {
        int idx = t + i * 256;            // 0..1023
        int r = idx >> 3, g = idx & 7;
        a_g[i] = g_ax + (size_t)(m0 + r) * K_DIM + g * 8;
        a_s[i] = sb + r * 128 + ((g ^ ((r & 3) << 1)) << 4);
    }
    const __half* b_g[8]; uint32_t b_s[8];
    #pragma unroll
    for (int i = 0; i < 8; i++) {
        int idx = t + i * 256;            // 0..2047
        int r = idx >> 3, g = idx & 7;
        b_g[i] = g_wt + (size_t)(n0 + r) * K_DIM + g * 8;
        b_s[i] = sb + A_STAGE_BYTES + r * 128 + ((g ^ ((r & 3) << 1)) << 4);
    }

    auto fill = [&](int s) {
        int off = (s & (SPIPE - 1)) * STAGE_BYTES;
        #pragma unroll
        for (int i = 0; i < 4; i++) cp16(a_s[i] + off, a_g[i] + s * BK);
        #pragma unroll
        for (int i = 0; i < 8; i++) cp16(b_s[i] + off, b_g[i] + s * BK);
        cp_commit();
    };

    fill(0); fill(1); fill(2);

    // fragment LDS.64: row r, kb -> byte = r*128 + ((4*kb + tg) ^ ((r&3)<<2))*8
    // all fragment rows have (r&3) == (g8&3)
    const int uxor = (g8 & 3) << 2;

    for (int s = 0; s < NSTAGES; s++) {
        if (s + 3 < NSTAGES) fill(s + 3); else cp_commit();
        cp_wait3();
        __syncthreads();

        const char* Ab = smem + (s & (SPIPE - 1)) * STAGE_BYTES;
        const char* Bb = Ab + A_STAGE_BYTES;

        #pragma unroll
        for (int kb = 0; kb < 4; kb++) {
            const int usw = ((4 * kb + tg) ^ uxor) << 3;   // swizzled 8B-unit byte offset
            uint32_t af[4][4];
            #pragma unroll
            for (int mi = 0; mi < 4; mi++) {
                int r = warp_m * 64 + mi * 16 + g8;
                uint2 v0 = *(const uint2*)(Ab + r * 128 + usw);
                uint2 v1 = *(const uint2*)(Ab + (r + 8) * 128 + usw);
                af[mi][0] = v0.x;   // (r,    k-lo pair)
                af[mi][1] = v1.x;   // (r+8,  k-lo pair)
                af[mi][2] = v0.y;   // (r,    k-hi pair)
                af[mi][3] = v1.y;   // (r+8,  k-hi pair)
            }
            uint32_t bf[8][2];
            #pragma unroll
            for (int ni = 0; ni < 8; ni++) {
                int r = warp_n * 64 + ni * 8 + g8;
                uint2 v = *(const uint2*)(Bb + r * 128 + usw);
                bf[ni][0] = v.x;
                bf[ni][1] = v.y;
            }
            #pragma unroll
            for (int mi = 0; mi < 4; mi++)
                #pragma unroll
                for (int ni = 0; ni < 8; ni++) {
                    asm volatile(
                        "mma.sync.aligned.m16n8k16.row.col.f32.f16.f16.f32 "
                        "{%0,%1,%2,%3}, {%4,%5,%6,%7}, {%8,%9}, {%0,%1,%2,%3};"
                        : "+f"(c[mi][ni][0]), "+f"(c[mi][ni][1]),
                          "+f"(c[mi][ni][2]), "+f"(c[mi][ni][3])
                        : "r"(af[mi][0]), "r"(af[mi][1]), "r"(af[mi][2]), "r"(af[mi][3]),
                          "r"(bf[ni][0]), "r"(bf[ni][1]));
                }
        }
    }

    // ---- epilogue ----
    #pragma unroll
    for (int mi = 0; mi < 4; mi++) {
        int row = m0 + warp_m * 64 + mi * 16 + g8;
        float* o0 = out + (size_t)row * N_DIM;
        float* o1 = out + (size_t)(row + 8) * N_DIM;
        #pragma unroll
        for (int ni = 0; ni < 8; ni++) {
            int col = n0 + warp_n * 64 + ni * 8 + 2 * tg;
            *(float2*)(o0 + col) = make_float2(c[mi][ni][0], c[mi][ni][1]);
            *(float2*)(o1 + col) = make_float2(c[mi][ni][2], c[mi][ni][3]);
        }
    }
}

// ---------------- launch ----------------
extern "C" void kernel_launch(void* const* d_in, const int* in_sizes, int n_in,
                              void* d_out, int out_size) {
    const float*    x       = (const float*)d_in[0];
    const uint32_t* qweight = (const uint32_t*)d_in[1];
    const float*    scales  = (const float*)d_in[2];
    const uint32_t* qzeros  = (const uint32_t*)d_in[3];
    float*          out     = (float*)d_out;

    cudaFuncSetAttribute(qgemm_f16,
                         cudaFuncAttributeMaxDynamicSharedMemorySize, SMEM_TOTAL);

    prep_kernel<<<PREP_A_BLOCKS + PREP_W_BLOCKS, 256>>>((const float4*)x, qweight, scales, qzeros);
    qgemm_f16<<<MTILES * NTILES, 256, SMEM_TOTAL>>>(out);
}